// round 16
// baseline (speedup 1.0000x reference)
#include <cuda_runtime.h>
#include <cuda_fp16.h>
#include <cstdint>

#define HID   512
#define SRC   2048
#define BATCH 64

// A-persistent CTA: M=128 (s-rows) x N=512 (all o) x K=512.
// A16: 8 chunks of 128x64 fp16 (16KB, XOR-swizzled) -> 128KB resident.
// B:   3-slot cp.async ring of 128x64 fp16 (16KB, XOR-swizzled).
// 32 stages g: nb = g>>3, kc = (g&7)*64.
#define KC        64
#define CHUNK_SZ  16384
#define B_SLOT    16384
#define OFF_A16   0                      // 8 chunks: 131072
#define OFF_B     131072                 // 3 slots:  49152
#define SMEM_BYTES 180224                // 176 KB -> 1 CTA/SM

// ---------------- device scratch ----------------
__device__ __align__(16) __half g_W1h[HID * HID];
__device__ float g_cbias[BATCH * HID];
__device__ float g_part[8][BATCH][SRC];   // plane = nb*2 + warp_n

// ---------------- helpers ----------------
__device__ __forceinline__ unsigned smem_u32(const void* p) {
    return (unsigned)__cvta_generic_to_shared(p);
}
__device__ __forceinline__ void ldsm4(uint32_t r[4], unsigned addr) {
    asm volatile("ldmatrix.sync.aligned.m8n8.x4.shared.b16 {%0,%1,%2,%3}, [%4];"
                 : "=r"(r[0]), "=r"(r[1]), "=r"(r[2]), "=r"(r[3]) : "r"(addr));
}
__device__ __forceinline__ void mma_fp16(float c[4], const uint32_t a[4], const uint32_t b[2]) {
    asm volatile(
        "mma.sync.aligned.m16n8k16.row.col.f32.f16.f16.f32 "
        "{%0,%1,%2,%3}, {%4,%5,%6,%7}, {%8,%9}, {%0,%1,%2,%3};"
        : "+f"(c[0]), "+f"(c[1]), "+f"(c[2]), "+f"(c[3])
        : "r"(a[0]), "r"(a[1]), "r"(a[2]), "r"(a[3]), "r"(b[0]), "r"(b[1]));
}
__device__ __forceinline__ void cp_async16(uint32_t dst, const void* src) {
    asm volatile("cp.async.cg.shared.global [%0], [%1], 16;" :: "r"(dst), "l"(src) : "memory");
}
__device__ __forceinline__ void cp_commit() {
    asm volatile("cp.async.commit_group;" ::: "memory");
}
__device__ __forceinline__ uint32_t packh2(float a, float b) {
    __half2 h = __floats2half2_rn(a, b);
    return *reinterpret_cast<uint32_t*>(&h);
}

// ---------------- kernel 1: W1 -> fp16 ----------------
__global__ void prep_w_kernel(const float* __restrict__ W1w) {
    int i = blockIdx.x * blockDim.x + threadIdx.x;
    if (i < HID * HID) g_W1h[i] = __float2half_rn(W1w[i]);
}

// ---------------- kernel 2: cbias ----------------
__global__ void cbias_kernel(const float* __restrict__ h,
                             const float* __restrict__ W2w,
                             const float* __restrict__ W2b,
                             const float* __restrict__ W1b) {
    __shared__ float hs[HID];
    const int b = blockIdx.x;
    const int o = blockIdx.y * 128 + threadIdx.x;
    for (int k = threadIdx.x; k < HID; k += 128) hs[k] = h[b * HID + k];
    __syncthreads();
    float acc = W2b[o] + W1b[o];
    const float* wr = W2w + o * HID;
#pragma unroll 8
    for (int k = 0; k < HID; k++) acc += hs[k] * wr[k];
    g_cbias[b * HID + o] = acc;
}

// ---------------- kernel 3: A-persistent fused GEMM + tanh + V-dot ----------------
// grid (16 st, 64 b); 256 threads = 8 warps (4 M x 2 N) per 128x128 sub-tile.
__global__ __launch_bounds__(256, 1) void attn_main_kernel(const float* __restrict__ enc,
                                                           const float* __restrict__ Vw) {
    extern __shared__ __align__(128) char smem[];
    const uint32_t sb = smem_u32(smem);

    const int st  = blockIdx.x;
    const int b   = blockIdx.y;
    const int tid = threadIdx.x;
    const int lane = tid & 31;
    const int wid  = tid >> 5;
    const int warp_m = wid & 3;
    const int warp_n = wid >> 2;
    const int s0 = st * 128;

    const float* encRow = enc + (size_t)(b * SRC + s0) * HID;

    // A chunk staging: 8 float4 per thread (idx = tid + k*256; row = idx>>4, u = idx&15)
    float4 areg[8];
    auto ldgA = [&](int c) {
        const int kc = c * KC;
#pragma unroll
        for (int k = 0; k < 8; ++k) {
            const int idx = tid + k * 256;
            const int row = idx >> 4;
            const int u   = idx & 15;
            areg[k] = *reinterpret_cast<const float4*>(
                encRow + (size_t)row * HID + kc + u * 4);
        }
    };
    auto stsA = [&](int c) {
        const uint32_t base = sb + OFF_A16 + c * CHUNK_SZ;
#pragma unroll
        for (int k = 0; k < 8; ++k) {
            const int idx = tid + k * 256;
            const int row = idx >> 4;
            const int u8  = idx & 15;
            const int u16 = u8 >> 1;
            const uint32_t v0 = packh2(areg[k].x, areg[k].y);
            const uint32_t v1 = packh2(areg[k].z, areg[k].w);
            asm volatile("st.shared.v2.u32 [%0], {%1,%2};"
                         :: "r"(base + row * 128 + ((u16 ^ (row & 7)) << 4) + (u8 & 1) * 8),
                            "r"(v0), "r"(v1) : "memory");
        }
    };
    auto load_B = [&](int g) {
        const int o0 = (g >> 3) * 128;
        const int kc = (g & 7) * KC;
        const uint32_t bb = sb + OFF_B + (g % 3) * B_SLOT;
#pragma unroll
        for (int k = 0; k < 4; ++k) {
            const int p = tid + k * 256;
            const int row = p >> 3;
            const int u   = p & 7;
            cp_async16(bb + row * 128 + ((u ^ (row & 7)) << 4),
                       g_W1h + (size_t)(o0 + row) * HID + kc + u * 8);
        }
        cp_commit();
    };

    float acc[2][8][4];
#pragma unroll
    for (int i = 0; i < 2; i++)
#pragma unroll
        for (int j = 0; j < 8; j++)
#pragma unroll
            for (int r = 0; r < 4; r++) acc[i][j][r] = 0.f;

    // ---- prologue ----
    ldgA(0);
    load_B(0);
    load_B(1);
    stsA(0);
    ldgA(1);

    // ---- mainloop: 32 stages, one sync each ----
#pragma unroll 1
    for (int g = 0; g < 32; ++g) {
        if (g < 31) asm volatile("cp.async.wait_group 1;" ::: "memory");  // B(g) done
        else        asm volatile("cp.async.wait_group 0;" ::: "memory");
        if (g < 7) stsA(g + 1);
        __syncthreads();                  // publish B(g) slot + A chunk g+1
        if (g < 6) ldgA(g + 2);           // hidden under compute(g)
        if (g + 2 < 32) load_B(g + 2);    // slot (g+2)%3 free since last sync

        const uint32_t a16 = sb + OFF_A16 + (g & 7) * CHUNK_SZ;
        const uint32_t bb  = sb + OFF_B + (g % 3) * B_SLOT;
#pragma unroll
        for (int ks = 0; ks < KC; ks += 16) {
            uint32_t a[2][4];
#pragma unroll
            for (int mt = 0; mt < 2; mt++) {
                const int r = warp_m * 32 + mt * 16 + (lane & 15);
                const int u = (ks >> 3) + (lane >> 4);
                ldsm4(a[mt], a16 + r * 128 + ((u ^ (r & 7)) << 4));
            }
#pragma unroll
            for (int ntp = 0; ntp < 4; ntp++) {
                const int br = warp_n * 64 + ntp * 16 + ((lane >> 4) << 3) + (lane & 7);
                const int bu = (ks >> 3) + ((lane >> 3) & 1);
                uint32_t bh[4];
                ldsm4(bh, bb + br * 128 + ((bu ^ (br & 7)) << 4));
#pragma unroll
                for (int mt = 0; mt < 2; mt++) {
#pragma unroll
                    for (int half = 0; half < 2; half++) {
                        mma_fp16(acc[mt][ntp * 2 + half], a[mt], bh + 2 * half);
                    }
                }
            }
        }

        // ---- per-nb epilogue: no smem, no barriers; overlaps next B loads ----
        if ((g & 7) == 7) {
            const int nb = g >> 3;
            const int o0 = nb * 128;
            const float* cbRow = g_cbias + b * HID;
            float rowsum[2][2];
            rowsum[0][0] = rowsum[0][1] = rowsum[1][0] = rowsum[1][1] = 0.f;
#pragma unroll
            for (int nt = 0; nt < 8; nt++) {
                const int o = o0 + warp_n * 64 + nt * 8 + (lane & 3) * 2;
                const float cb0 = cbRow[o],     v0 = Vw[o];
                const float cb1 = cbRow[o + 1], v1 = Vw[o + 1];
#pragma unroll
                for (int mt = 0; mt < 2; mt++) {
                    rowsum[mt][0] += tanhf(acc[mt][nt][0] + cb0) * v0;
                    rowsum[mt][0] += tanhf(acc[mt][nt][1] + cb1) * v1;
                    rowsum[mt][1] += tanhf(acc[mt][nt][2] + cb0) * v0;
                    rowsum[mt][1] += tanhf(acc[mt][nt][3] + cb1) * v1;
                }
            }
#pragma unroll
            for (int mt = 0; mt < 2; mt++) {
#pragma unroll
                for (int j = 0; j < 2; j++) {
                    float v = rowsum[mt][j];
                    v += __shfl_xor_sync(0xffffffffu, v, 1);
                    v += __shfl_xor_sync(0xffffffffu, v, 2);
                    if ((lane & 3) == 0) {
                        const int row = warp_m * 32 + mt * 16 + (lane >> 2) + 8 * j;
                        g_part[nb * 2 + warp_n][b][s0 + row] = v;
                    }
                }
            }
#pragma unroll
            for (int i = 0; i < 2; i++)
#pragma unroll
                for (int j = 0; j < 8; j++)
#pragma unroll
                    for (int r = 0; r < 4; r++) acc[i][j][r] = 0.f;
        }
    }
}

// ---------------- kernel 4: sum 8 partials + softmax over S ----------------
__global__ void softmax_kernel(float* __restrict__ out) {
    __shared__ float sv[SRC];
    __shared__ float red[256];
    int b = blockIdx.x;
    int tid = threadIdx.x;

    float mx = -1e30f;
    for (int s = tid; s < SRC; s += 256) {
        float v = 0.f;
#pragma unroll
        for (int p = 0; p < 8; p++) v += g_part[p][b][s];
        sv[s] = v;
        mx = fmaxf(mx, v);
    }
    red[tid] = mx;
    __syncthreads();
    for (int st = 128; st > 0; st >>= 1) {
        if (tid < st) red[tid] = fmaxf(red[tid], red[tid + st]);
        __syncthreads();
    }
    mx = red[0];
    __syncthreads();

    float sum = 0.f;
    for (int s = tid; s < SRC; s += 256) {
        float e = expf(sv[s] - mx);
        sv[s] = e;
        sum += e;
    }
    red[tid] = sum;
    __syncthreads();
    for (int st = 128; st > 0; st >>= 1) {
        if (tid < st) red[tid] += red[tid + st];
        __syncthreads();
    }
    float inv = 1.0f / red[0];
    __syncthreads();

    for (int s = tid; s < SRC; s += 256) {
        out[(size_t)b * SRC + s] = sv[s] * inv;
    }
}

// ---------------- launch ----------------
extern "C" void kernel_launch(void* const* d_in, const int* in_sizes, int n_in,
                              void* d_out, int out_size) {
    const float* h    = (const float*)d_in[0];
    const float* enc  = (const float*)d_in[1];
    const float* W1w  = (const float*)d_in[2];
    const float* W1b  = (const float*)d_in[3];
    const float* W2w  = (const float*)d_in[4];
    const float* W2b  = (const float*)d_in[5];
    const float* Vw   = (const float*)d_in[6];
    float* out = (float*)d_out;

    cudaFuncSetAttribute(attn_main_kernel,
                         cudaFuncAttributeMaxDynamicSharedMemorySize, SMEM_BYTES);

    prep_w_kernel<<<(HID * HID + 511) / 512, 512>>>(W1w);
    cbias_kernel<<<dim3(BATCH, 4), 128>>>(h, W2w, W2b, W1b);
    attn_main_kernel<<<dim3(16, BATCH), 256, SMEM_BYTES>>>(enc, Vw);
    softmax_kernel<<<BATCH, 256>>>(out);
}